// round 15
// baseline (speedup 1.0000x reference)
#include <cuda_runtime.h>
#include <cuda_fp16.h>
#include <math.h>
#include <stdint.h>

#define BSZ 2
#define T   2048
#define E   1024
#define H   16
#define D   64

// fp16 attention intermediates
__device__ __half g_q[BSZ*T*E];          // Q proj, x0.125, dim-pair-interleaved
__device__ __half g_k[BSZ*T*E];          // K proj, dim-pair-interleaved
__device__ __half g_vT[BSZ*H*D*T];       // V proj transposed, token-interleaved
__device__ __half g_attn[BSZ*T*E];       // attn out, PLAIN row-major fp16
// fp16 PLAIN row-major GEMM inputs (prepass outputs)
__device__ __half g_haq[BSZ*T*E];
__device__ __half g_hak[BSZ*T*E];
__device__ __half g_hav[BSZ*T*E];
__device__ __half g_hwq[E*E];
__device__ __half g_hwk[E*E];
__device__ __half g_hwv[E*E];
__device__ __half g_hwo[E*E];

// ===========================================================================
// Helpers
// ===========================================================================
__device__ __forceinline__ uint32_t su32(const void* p) {
    return (uint32_t)__cvta_generic_to_shared(p);
}
__device__ __forceinline__ void mma16(float c[4], uint32_t a0, uint32_t a1,
                                      uint32_t a2, uint32_t a3,
                                      uint32_t b0, uint32_t b1) {
    asm("mma.sync.aligned.m16n8k16.row.col.f32.f16.f16.f32 "
        "{%0,%1,%2,%3},{%4,%5,%6,%7},{%8,%9},{%0,%1,%2,%3};"
        : "+f"(c[0]), "+f"(c[1]), "+f"(c[2]), "+f"(c[3])
        : "r"(a0), "r"(a1), "r"(a2), "r"(a3), "r"(b0), "r"(b1));
}
__device__ __forceinline__ void ldsm4(uint32_t& r0, uint32_t& r1,
                                      uint32_t& r2, uint32_t& r3, uint32_t addr) {
    asm volatile("ldmatrix.sync.aligned.m8n8.x4.shared.b16 {%0,%1,%2,%3}, [%4];"
                 : "=r"(r0), "=r"(r1), "=r"(r2), "=r"(r3) : "r"(addr));
}
__device__ __forceinline__ void cp16(uint32_t dst, const void* src) {
    asm volatile("cp.async.cg.shared.global [%0], [%1], 16;"
                 :: "r"(dst), "l"(src) : "memory");
}
__device__ __forceinline__ void cp_commit() {
    asm volatile("cp.async.commit_group;" ::: "memory");
}
template <int N>
__device__ __forceinline__ void cp_wait() {
    asm volatile("cp.async.wait_group %0;" :: "n"(N) : "memory");
}
__device__ __forceinline__ uint32_t h2u(__half2 h) { return *(uint32_t*)&h; }

// ===========================================================================
// Prepass: plain fp32 -> fp16 convert (8 elems / thread)
// ===========================================================================
struct PPArgs {
    const float* src[7];
    __half*      dst[7];
    int          ngrp[7];
};

__global__ __launch_bounds__(256) void prepass(PPArgs a) {
    const int z = blockIdx.z;
    const int i = blockIdx.x * 256 + threadIdx.x;
    if (i >= a.ngrp[z]) return;
    const float4* s = (const float4*)a.src[z] + (size_t)i * 2;
    float4 f0 = s[0], f1 = s[1];
    uint4 o;
    o.x = h2u(__floats2half2_rn(f0.x, f0.y));
    o.y = h2u(__floats2half2_rn(f0.z, f0.w));
    o.z = h2u(__floats2half2_rn(f1.x, f1.y));
    o.w = h2u(__floats2half2_rn(f1.z, f1.w));
    *(uint4*)(a.dst[z] + (size_t)i * 8) = o;
}

// ===========================================================================
// fp16 m16n8k16 GEMM, ldmatrix.x4 loads, 512 threads (16 warps = 4/SMSP).
// CTA 256x128, warp tile 32x64 (wr=wid&7: 8 m-groups x 32; wc=wid>>3: 2
// n-groups x 64), BK=64 halves, 3-stage. Smem plain row-major 128 B rows,
// chunk-XOR swizzle (ch ^ (row&7)) -> LDSM conflict-free, cp.async clean.
// Per kc: 6 LDSM.x4 + 16 mma. ~110 regs/thread -> 512 thr fits RF.
// mode 0: fp32 out; 2: fp16 x0.125 dim-interleaved (Q);
// 3: fp16 dim-interleaved (K); 4: fp16 V^T token-interleaved.
// ===========================================================================
#define KDIM 1024
#define MT   256
#define NT   128
#define BKH  64
#define ROWB 128
#define STAGEB ((MT+NT)*ROWB)                 // 49152 B
#define G_SMEM (3*STAGEB)                     // 147456 B

__device__ __forceinline__ void gemm_core(const __half* __restrict__ A,
                                          const __half* __restrict__ W,
                                          float* __restrict__ Cf,
                                          __half* __restrict__ Ch,
                                          int mode, __half* sg) {
    const uint32_t sbase = su32(sg);
    const int tid  = threadIdx.x;
    const int wid  = tid >> 5, lane = tid & 31;
    const int g    = lane >> 2, q = lane & 3;
    const int wr   = wid & 7;          // 8 m-groups x 32 rows
    const int wc   = wid >> 3;         // 2 n-groups x 64 cols
    const int bm   = blockIdx.y * MT;
    const int bn   = blockIdx.x * NT;

    const __half* gA = A + (size_t)bm * KDIM;
    const __half* gW = W + (size_t)bn * KDIM;

    auto cp_stage = [&](int s, int kt) {
        const uint32_t base = sbase + s * STAGEB;
        const int k0 = kt * BKH;
        #pragma unroll
        for (int i = 0; i < 6; i++) {
            int c = tid + i * 512;               // 0..3071
            int row = c >> 3, ch = c & 7;
            uint32_t phys = base + row * ROWB + ((ch ^ (row & 7)) << 4);
            const __half* src = (row < MT)
                ? gA + (size_t)row * KDIM + k0 + ch * 8
                : gW + (size_t)(row - MT) * KDIM + k0 + ch * 8;
            cp16(phys, src);
        }
        cp_commit();
    };

    float acc[2][8][4];
    #pragma unroll
    for (int mi = 0; mi < 2; mi++)
        #pragma unroll
        for (int ni = 0; ni < 8; ni++)
            #pragma unroll
            for (int e = 0; e < 4; e++) acc[mi][ni][e] = 0.f;

    // ldmatrix per-lane address components
    const int swz  = lane & 7;
    const int arow = wr * 32 + (lane & 7) + 8 * ((lane >> 3) & 1);
    const int asel = lane >> 4;                  // k-chunk half (0/1)
    const int brow = wc * 64 + (lane & 7) + 8 * (lane >> 4);
    const int bsel = (lane >> 3) & 1;

    cp_stage(0, 0); cp_stage(1, 1);

    const int NKT = KDIM / BKH;   // 16
    int buf = 0;
    for (int kt = 0; kt < NKT; kt++) {
        cp_wait<1>();
        __syncthreads();
        if (kt + 2 < NKT) {
            int nb = buf + 2; if (nb >= 3) nb -= 3;
            cp_stage(nb, kt + 2);
        } else cp_commit();

        const uint32_t As = sbase + buf * STAGEB;
        const uint32_t Ws = As + MT * ROWB;
        const uint32_t aB = As + arow * ROWB;
        const uint32_t bB = Ws + brow * ROWB;

        #pragma unroll
        for (int kc = 0; kc < 4; kc++) {
            const uint32_t aoff = (uint32_t)(((2*kc + asel) ^ swz) << 4);
            const uint32_t boff = (uint32_t)(((2*kc + bsel) ^ swz) << 4);
            uint32_t av[2][4];
            #pragma unroll
            for (int mi = 0; mi < 2; mi++)
                ldsm4(av[mi][0], av[mi][1], av[mi][2], av[mi][3],
                      aB + mi * (16 * ROWB) + aoff);
            #pragma unroll
            for (int np = 0; np < 4; np++) {
                uint32_t b0, b1, b2, b3;
                ldsm4(b0, b1, b2, b3, bB + np * (16 * ROWB) + boff);
                #pragma unroll
                for (int mi = 0; mi < 2; mi++) {
                    mma16(acc[mi][2*np],   av[mi][0], av[mi][1], av[mi][2], av[mi][3], b0, b1);
                    mma16(acc[mi][2*np+1], av[mi][0], av[mi][1], av[mi][2], av[mi][3], b2, b3);
                }
            }
        }
        buf++; if (buf == 3) buf = 0;
    }

    if (mode == 0) {
        #pragma unroll
        for (int mi = 0; mi < 2; mi++) {
            const int r0 = bm + wr * 32 + mi * 16 + g;
            #pragma unroll
            for (int ni = 0; ni < 8; ni++) {
                const int colb = bn + wc * 64 + ni * 8;
                *(float2*)(Cf + (size_t)r0 * E + colb + 2*q) =
                    make_float2(acc[mi][ni][0], acc[mi][ni][1]);
                *(float2*)(Cf + (size_t)(r0+8) * E + colb + 2*q) =
                    make_float2(acc[mi][ni][2], acc[mi][ni][3]);
            }
        }
    } else if (mode == 4) {
        const int slot0 = 4 * (g >> 1) + (g & 1);
        const int slot1 = slot0 + 2;
        #pragma unroll
        for (int mi = 0; mi < 2; mi++) {
            const int tk0 = bm + wr * 32 + mi * 16 + g;
            const int bi  = tk0 >> 11;
            const int tl  = (tk0 & 2047) & ~15;
            #pragma unroll
            for (int ni = 0; ni < 8; ni++) {
                const int c0 = bn + wc * 64 + ni * 8 + 2 * q;
                const int hh = c0 >> 6, d0 = c0 & 63;
                __half* bp = Ch + ((size_t)(bi * H + hh) * D) * T;
                bp[(size_t)d0 * T + tl + slot0]       = __float2half(acc[mi][ni][0]);
                bp[(size_t)(d0 + 1) * T + tl + slot0] = __float2half(acc[mi][ni][1]);
                bp[(size_t)d0 * T + tl + slot1]       = __float2half(acc[mi][ni][2]);
                bp[(size_t)(d0 + 1) * T + tl + slot1] = __float2half(acc[mi][ni][3]);
            }
        }
    } else {
        const float sc = (mode == 2) ? 0.125f : 1.0f;
        #pragma unroll
        for (int mi = 0; mi < 2; mi++) {
            const int r0 = bm + wr * 32 + mi * 16 + g;
            #pragma unroll
            for (int ni = 0; ni < 8; ni++) {
                const int base = bn + wc * 64 + ((ni >> 1) << 4) + 4*q + 2*(ni & 1);
                *(__half2*)(Ch + (size_t)r0 * E + base) =
                    __floats2half2_rn(sc * acc[mi][ni][0], sc * acc[mi][ni][1]);
                *(__half2*)(Ch + (size_t)(r0+8) * E + base) =
                    __floats2half2_rn(sc * acc[mi][ni][2], sc * acc[mi][ni][3]);
            }
        }
    }
}

__global__ __launch_bounds__(512, 1) void gemm_qkv() {
    extern __shared__ __half sg[];
    if (blockIdx.z == 0)      gemm_core(g_haq, g_hwq, nullptr, g_q,  2, sg);
    else if (blockIdx.z == 1) gemm_core(g_hak, g_hwk, nullptr, g_k,  3, sg);
    else                      gemm_core(g_hav, g_hwv, nullptr, g_vT, 4, sg);
}

__global__ __launch_bounds__(512, 1) void gemm_out(float* __restrict__ C) {
    extern __shared__ __half sg[];
    gemm_core(g_attn, g_hwo, C, nullptr, 0, sg);
}

// ===========================================================================
// Causal flash attention, fp16 m16n8k16, fp32 accum (unchanged from R14).
// ===========================================================================
#define AKH (64*80)
#define AKB (AKH*2)
#define A_SMEM (4*AKB)                    // 40960 B

__global__ __launch_bounds__(256, 2) void attn_tc() {
    extern __shared__ __half sh[];
    const uint32_t sbase = su32(sh);

    const int tid = threadIdx.x;
    const int w = tid >> 5, lane = tid & 31;
    const int g = lane >> 2, q = lane & 3;
    const int b = blockIdx.y / H, h = blockIdx.y % H;
    const int qt = gridDim.x - 1 - blockIdx.x;
    const int qbase = qt * 128;
    const int jmax = 2 * qt + 1;

    const __half* Kg  = g_k + (size_t)(b * T) * E + h * D;
    const __half* Vtg = g_vT + (size_t)((b * H + h) * D) * T;

    const __half* Q0 = g_q + (size_t)(b * T + qbase + w * 16 + g) * E + h * D;
    uint32_t qa[4][4];
    #pragma unroll
    for (int kc = 0; kc < 4; kc++) {
        uint2 x0 = *(const uint2*)&Q0[kc * 16 + 4 * q];
        uint2 x1 = *(const uint2*)&Q0[(size_t)8 * E + kc * 16 + 4 * q];
        qa[kc][0] = x0.x; qa[kc][1] = x1.x; qa[kc][2] = x0.y; qa[kc][3] = x1.y;
    }

    auto stage = [&](int j) {
        const int buf = j & 1;
        const int kbase = j * 64;
        const uint32_t kdst = sbase + buf * AKB;
        const uint32_t vdst = sbase + (2 + buf) * AKB;
        #pragma unroll
        for (int t = 0; t < 4; t++) {
            int c = tid + t * 256;
            if (c < 512) {
                int row = c >> 3, ch = c & 7;
                cp16(kdst + row * 160 + ch * 16,
                     Kg + (size_t)(kbase + row) * E + ch * 8);
            } else {
                int cc = c - 512;
                int row = cc >> 3, ch = cc & 7;
                cp16(vdst + row * 160 + ch * 16,
                     Vtg + (size_t)row * T + kbase + ch * 8);
            }
        }
        cp_commit();
    };

    float oacc[8][4];
    #pragma unroll
    for (int nt = 0; nt < 8; nt++)
        #pragma unroll
        for (int e = 0; e < 4; e++) oacc[nt][e] = 0.f;

    float m0 = -INFINITY, m1 = -INFINITY, l0 = 0.f, l1 = 0.f;
    const int r0g = qbase + w * 16 + g, r1g = r0g + 8;
    const int wmaxrow = qbase + w * 16 + 15;

    stage(0);

    for (int j = 0; j <= jmax; j++) {
        __syncthreads();
        if (j < jmax) stage(j + 1);
        else          cp_commit();
        cp_wait<1>();
        __syncthreads();

        const int kbase = j * 64;
        if (kbase > wmaxrow) continue;

        const __half* Ks = sh + (j & 1) * AKH;
        const __half* Vs = sh + (2 + (j & 1)) * AKH;

        float sacc[8][4];
        #pragma unroll
        for (int nt = 0; nt < 8; nt++) {
            #pragma unroll
            for (int e = 0; e < 4; e++) sacc[nt][e] = 0.f;
            const __half* kp = Ks + (nt * 8 + g) * 80 + 4 * q;
            #pragma unroll
            for (int kc = 0; kc < 4; kc++) {
                uint2 kb = *(const uint2*)&kp[kc * 16];
                mma16(sacc[nt], qa[kc][0], qa[kc][1], qa[kc][2], qa[kc][3],
                      kb.x, kb.y);
            }
        }

        if (kbase + 63 > r0g) {
            #pragma unroll
            for (int nt = 0; nt < 8; nt++) {
                #pragma unroll
                for (int e = 0; e < 2; e++) {
                    int colg = kbase + nt * 8 + 2 * q + e;
                    if (colg > r0g) sacc[nt][e]     = -INFINITY;
                    if (colg > r1g) sacc[nt][2 + e] = -INFINITY;
                }
            }
        }

        float mx0 = -INFINITY, mx1 = -INFINITY;
        #pragma unroll
        for (int nt = 0; nt < 8; nt++) {
            mx0 = fmaxf(mx0, fmaxf(sacc[nt][0], sacc[nt][1]));
            mx1 = fmaxf(mx1, fmaxf(sacc[nt][2], sacc[nt][3]));
        }
        mx0 = fmaxf(mx0, __shfl_xor_sync(0xffffffffu, mx0, 1));
        mx0 = fmaxf(mx0, __shfl_xor_sync(0xffffffffu, mx0, 2));
        mx1 = fmaxf(mx1, __shfl_xor_sync(0xffffffffu, mx1, 1));
        mx1 = fmaxf(mx1, __shfl_xor_sync(0xffffffffu, mx1, 2));
        float mn0 = fmaxf(m0, mx0), mn1 = fmaxf(m1, mx1);
        float sc0 = __expf(m0 - mn0), sc1 = __expf(m1 - mn1);

        float s0 = 0.f, s1 = 0.f;
        uint32_t ph[8][2];
        #pragma unroll
        for (int nt = 0; nt < 8; nt++) {
            float p0 = __expf(sacc[nt][0] - mn0);
            float p1 = __expf(sacc[nt][1] - mn0);
            float p2 = __expf(sacc[nt][2] - mn1);
            float p3 = __expf(sacc[nt][3] - mn1);
            s0 += p0 + p1; s1 += p2 + p3;
            ph[nt][0] = h2u(__floats2half2_rn(p0, p1));
            ph[nt][1] = h2u(__floats2half2_rn(p2, p3));
        }
        s0 += __shfl_xor_sync(0xffffffffu, s0, 1);
        s0 += __shfl_xor_sync(0xffffffffu, s0, 2);
        s1 += __shfl_xor_sync(0xffffffffu, s1, 1);
        s1 += __shfl_xor_sync(0xffffffffu, s1, 2);
        l0 = l0 * sc0 + s0; l1 = l1 * sc1 + s1;
        m0 = mn0; m1 = mn1;
        #pragma unroll
        for (int nt = 0; nt < 8; nt++) {
            oacc[nt][0] *= sc0; oacc[nt][1] *= sc0;
            oacc[nt][2] *= sc1; oacc[nt][3] *= sc1;
        }

        #pragma unroll
        for (int nt = 0; nt < 8; nt++) {
            const __half* vp = Vs + (nt * 8 + g) * 80 + 4 * q;
            #pragma unroll
            for (int kc = 0; kc < 4; kc++) {
                uint2 vb = *(const uint2*)&vp[kc * 16];
                mma16(oacc[nt], ph[2*kc][0], ph[2*kc][1],
                      ph[2*kc+1][0], ph[2*kc+1][1], vb.x, vb.y);
            }
        }
    }

    const float inv0 = 1.f / l0, inv1 = 1.f / l1;
    __half* O0 = g_attn + ((size_t)(b * T + r0g)) * E + h * D;
    __half* O1 = g_attn + ((size_t)(b * T + r1g)) * E + h * D;
    #pragma unroll
    for (int nt = 0; nt < 8; nt++) {
        *(__half2*)(O0 + nt * 8 + 2 * q) =
            __floats2half2_rn(oacc[nt][0] * inv0, oacc[nt][1] * inv0);
        *(__half2*)(O1 + nt * 8 + 2 * q) =
            __floats2half2_rn(oacc[nt][2] * inv1, oacc[nt][3] * inv1);
    }
}

// ===========================================================================
// Inputs: queries, keys, values, mask(unused), Wq, Wk, Wv, Wo
// ===========================================================================
extern "C" void kernel_launch(void* const* d_in, const int* in_sizes, int n_in,
                              void* d_out, int out_size) {
    const float* queries = (const float*)d_in[0];
    const float* keys    = (const float*)d_in[1];
    const float* values  = (const float*)d_in[2];
    const float* Wq      = (const float*)d_in[4];
    const float* Wk      = (const float*)d_in[5];
    const float* Wv      = (const float*)d_in[6];
    const float* Wo      = (const float*)d_in[7];

    __half *haq, *hak, *hav, *hwq, *hwk, *hwv, *hwo;
    cudaGetSymbolAddress((void**)&haq, g_haq);
    cudaGetSymbolAddress((void**)&hak, g_hak);
    cudaGetSymbolAddress((void**)&hav, g_hav);
    cudaGetSymbolAddress((void**)&hwq, g_hwq);
    cudaGetSymbolAddress((void**)&hwk, g_hwk);
    cudaGetSymbolAddress((void**)&hwv, g_hwv);
    cudaGetSymbolAddress((void**)&hwo, g_hwo);

    static bool attr_set = false;
    if (!attr_set) {
        cudaFuncSetAttribute(gemm_qkv, cudaFuncAttributeMaxDynamicSharedMemorySize, (int)G_SMEM);
        cudaFuncSetAttribute(gemm_out, cudaFuncAttributeMaxDynamicSharedMemorySize, (int)G_SMEM);
        cudaFuncSetAttribute(attn_tc,  cudaFuncAttributeMaxDynamicSharedMemorySize, (int)A_SMEM);
        attr_set = true;
    }

    PPArgs pa;
    const int NG_IN = BSZ * T * E / 8;
    const int NG_W  = E * E / 8;
    pa.src[0] = queries; pa.dst[0] = haq; pa.ngrp[0] = NG_IN;
    pa.src[1] = keys;    pa.dst[1] = hak; pa.ngrp[1] = NG_IN;
    pa.src[2] = values;  pa.dst[2] = hav; pa.ngrp[2] = NG_IN;
    pa.src[3] = Wq;      pa.dst[3] = hwq; pa.ngrp[3] = NG_W;
    pa.src[4] = Wk;      pa.dst[4] = hwk; pa.ngrp[4] = NG_W;
    pa.src[5] = Wv;      pa.dst[5] = hwv; pa.ngrp[5] = NG_W;
    pa.src[6] = Wo;      pa.dst[6] = hwo; pa.ngrp[6] = NG_W;
    prepass<<<dim3(NG_IN / 256, 1, 7), 256>>>(pa);

    dim3 gq(E / NT, (BSZ * T) / MT, 3);     // (8, 16, 3) = 384 CTAs
    gemm_qkv<<<gq, 512, G_SMEM>>>();

    attn_tc<<<dim3(T / 128, BSZ * H), 256, A_SMEM>>>();

    dim3 gg(E / NT, (BSZ * T) / MT);        // (8, 16) = 128 CTAs
    gemm_out<<<gg, 512, G_SMEM>>>((float*)d_out);
}

// round 16
// speedup vs baseline: 1.0211x; 1.0211x over previous
#include <cuda_runtime.h>
#include <cuda_fp16.h>
#include <math.h>
#include <stdint.h>

#define BSZ 2
#define T   2048
#define E   1024
#define H   16
#define D   64

// fp16 attention intermediates
__device__ __half g_q[BSZ*T*E];          // Q proj, x0.125, dim-pair-interleaved
__device__ __half g_k[BSZ*T*E];          // K proj, PLAIN row-major
__device__ __half g_vT[BSZ*H*D*T];       // V proj transposed [b,h,d,t], PLAIN
__device__ __half g_attn[BSZ*T*E];       // attn out, PLAIN row-major fp16
// fp16 PLAIN row-major GEMM inputs (prepass outputs)
__device__ __half g_haq[BSZ*T*E];
__device__ __half g_hak[BSZ*T*E];
__device__ __half g_hav[BSZ*T*E];
__device__ __half g_hwq[E*E];
__device__ __half g_hwk[E*E];
__device__ __half g_hwv[E*E];
__device__ __half g_hwo[E*E];

// ===========================================================================
// Helpers
// ===========================================================================
__device__ __forceinline__ uint32_t su32(const void* p) {
    return (uint32_t)__cvta_generic_to_shared(p);
}
__device__ __forceinline__ void mma16(float c[4], uint32_t a0, uint32_t a1,
                                      uint32_t a2, uint32_t a3,
                                      uint32_t b0, uint32_t b1) {
    asm("mma.sync.aligned.m16n8k16.row.col.f32.f16.f16.f32 "
        "{%0,%1,%2,%3},{%4,%5,%6,%7},{%8,%9},{%0,%1,%2,%3};"
        : "+f"(c[0]), "+f"(c[1]), "+f"(c[2]), "+f"(c[3])
        : "r"(a0), "r"(a1), "r"(a2), "r"(a3), "r"(b0), "r"(b1));
}
__device__ __forceinline__ void ldsm4(uint32_t& r0, uint32_t& r1,
                                      uint32_t& r2, uint32_t& r3, uint32_t addr) {
    asm volatile("ldmatrix.sync.aligned.m8n8.x4.shared.b16 {%0,%1,%2,%3}, [%4];"
                 : "=r"(r0), "=r"(r1), "=r"(r2), "=r"(r3) : "r"(addr));
}
__device__ __forceinline__ void cp16(uint32_t dst, const void* src) {
    asm volatile("cp.async.cg.shared.global [%0], [%1], 16;"
                 :: "r"(dst), "l"(src) : "memory");
}
__device__ __forceinline__ void cp_commit() {
    asm volatile("cp.async.commit_group;" ::: "memory");
}
template <int N>
__device__ __forceinline__ void cp_wait() {
    asm volatile("cp.async.wait_group %0;" :: "n"(N) : "memory");
}
__device__ __forceinline__ uint32_t h2u(__half2 h) { return *(uint32_t*)&h; }

// ===========================================================================
// Prepass: plain fp32 -> fp16 convert (8 elems / thread)
// ===========================================================================
struct PPArgs {
    const float* src[7];
    __half*      dst[7];
    int          ngrp[7];
};

__global__ __launch_bounds__(256) void prepass(PPArgs a) {
    const int z = blockIdx.z;
    const int i = blockIdx.x * 256 + threadIdx.x;
    if (i >= a.ngrp[z]) return;
    const float4* s = (const float4*)a.src[z] + (size_t)i * 2;
    float4 f0 = s[0], f1 = s[1];
    uint4 o;
    o.x = h2u(__floats2half2_rn(f0.x, f0.y));
    o.y = h2u(__floats2half2_rn(f0.z, f0.w));
    o.z = h2u(__floats2half2_rn(f1.x, f1.y));
    o.w = h2u(__floats2half2_rn(f1.z, f1.w));
    *(uint4*)(a.dst[z] + (size_t)i * 8) = o;
}

// ===========================================================================
// fp16 m16n8k16 GEMM, ldmatrix.x4 loads (R14 config: best measured).
// CTA 256x128, 256 thr (8 warps), warp tile 64x64, BK=64 halves, 3-stage.
// Smem plain row-major 128 B rows, chunk-XOR swizzle (ch ^ (row&7)).
// mode 0: fp32 out; 2: fp16 x0.125 dim-interleaved (Q);
// 3: fp16 PLAIN (K); 4: fp16 V^T PLAIN transposed.
// ===========================================================================
#define KDIM 1024
#define MT   256
#define NT   128
#define BKH  64
#define ROWB 128
#define STAGEB ((MT+NT)*ROWB)                 // 49152 B
#define G_SMEM (3*STAGEB)                     // 147456 B

__device__ __forceinline__ void gemm_core(const __half* __restrict__ A,
                                          const __half* __restrict__ W,
                                          float* __restrict__ Cf,
                                          __half* __restrict__ Ch,
                                          int mode, __half* sg) {
    const uint32_t sbase = su32(sg);
    const int tid  = threadIdx.x;
    const int wid  = tid >> 5, lane = tid & 31;
    const int g    = lane >> 2, q = lane & 3;
    const int wr   = wid & 3;          // 4 m-groups x 64 rows
    const int wc   = wid >> 2;         // 2 n-groups x 64 cols
    const int bm   = blockIdx.y * MT;
    const int bn   = blockIdx.x * NT;

    const __half* gA = A + (size_t)bm * KDIM;
    const __half* gW = W + (size_t)bn * KDIM;

    auto cp_stage = [&](int s, int kt) {
        const uint32_t base = sbase + s * STAGEB;
        const int k0 = kt * BKH;
        #pragma unroll
        for (int i = 0; i < 12; i++) {
            int c = tid + i * 256;               // 0..3071
            int row = c >> 3, ch = c & 7;
            uint32_t phys = base + row * ROWB + ((ch ^ (row & 7)) << 4);
            const __half* src = (row < MT)
                ? gA + (size_t)row * KDIM + k0 + ch * 8
                : gW + (size_t)(row - MT) * KDIM + k0 + ch * 8;
            cp16(phys, src);
        }
        cp_commit();
    };

    float acc[4][8][4];
    #pragma unroll
    for (int mi = 0; mi < 4; mi++)
        #pragma unroll
        for (int ni = 0; ni < 8; ni++)
            #pragma unroll
            for (int e = 0; e < 4; e++) acc[mi][ni][e] = 0.f;

    const int swz  = lane & 7;
    const int arow = wr * 64 + (lane & 7) + 8 * ((lane >> 3) & 1);
    const int asel = lane >> 4;
    const int brow = wc * 64 + (lane & 7) + 8 * (lane >> 4);
    const int bsel = (lane >> 3) & 1;

    cp_stage(0, 0); cp_stage(1, 1);

    const int NKT = KDIM / BKH;   // 16
    int buf = 0;
    for (int kt = 0; kt < NKT; kt++) {
        cp_wait<1>();
        __syncthreads();
        if (kt + 2 < NKT) {
            int nb = buf + 2; if (nb >= 3) nb -= 3;
            cp_stage(nb, kt + 2);
        } else cp_commit();

        const uint32_t As = sbase + buf * STAGEB;
        const uint32_t Ws = As + MT * ROWB;
        const uint32_t aB = As + arow * ROWB;
        const uint32_t bB = Ws + brow * ROWB;

        #pragma unroll
        for (int kc = 0; kc < 4; kc++) {
            const uint32_t aoff = (uint32_t)(((2*kc + asel) ^ swz) << 4);
            const uint32_t boff = (uint32_t)(((2*kc + bsel) ^ swz) << 4);
            uint32_t av[4][4];
            #pragma unroll
            for (int mi = 0; mi < 4; mi++)
                ldsm4(av[mi][0], av[mi][1], av[mi][2], av[mi][3],
                      aB + mi * (16 * ROWB) + aoff);
            #pragma unroll
            for (int np = 0; np < 4; np++) {
                uint32_t b0, b1, b2, b3;
                ldsm4(b0, b1, b2, b3, bB + np * (16 * ROWB) + boff);
                #pragma unroll
                for (int mi = 0; mi < 4; mi++) {
                    mma16(acc[mi][2*np],   av[mi][0], av[mi][1], av[mi][2], av[mi][3], b0, b1);
                    mma16(acc[mi][2*np+1], av[mi][0], av[mi][1], av[mi][2], av[mi][3], b2, b3);
                }
            }
        }
        buf++; if (buf == 3) buf = 0;
    }

    if (mode == 0) {
        #pragma unroll
        for (int mi = 0; mi < 4; mi++) {
            const int r0 = bm + wr * 64 + mi * 16 + g;
            #pragma unroll
            for (int ni = 0; ni < 8; ni++) {
                const int colb = bn + wc * 64 + ni * 8;
                *(float2*)(Cf + (size_t)r0 * E + colb + 2*q) =
                    make_float2(acc[mi][ni][0], acc[mi][ni][1]);
                *(float2*)(Cf + (size_t)(r0+8) * E + colb + 2*q) =
                    make_float2(acc[mi][ni][2], acc[mi][ni][3]);
            }
        }
    } else if (mode == 3) {
        // K: plain fp16 row-major
        #pragma unroll
        for (int mi = 0; mi < 4; mi++) {
            const int r0 = bm + wr * 64 + mi * 16 + g;
            #pragma unroll
            for (int ni = 0; ni < 8; ni++) {
                const int colb = bn + wc * 64 + ni * 8;
                *(__half2*)(Ch + (size_t)r0 * E + colb + 2*q) =
                    __floats2half2_rn(acc[mi][ni][0], acc[mi][ni][1]);
                *(__half2*)(Ch + (size_t)(r0+8) * E + colb + 2*q) =
                    __floats2half2_rn(acc[mi][ni][2], acc[mi][ni][3]);
            }
        }
    } else if (mode == 4) {
        // V^T: plain [b, h, dim, token]
        #pragma unroll
        for (int mi = 0; mi < 4; mi++) {
            const int tk0 = bm + wr * 64 + mi * 16 + g;
            const int bi  = tk0 >> 11;
            const int tl  = tk0 & 2047;
            #pragma unroll
            for (int ni = 0; ni < 8; ni++) {
                const int c0 = bn + wc * 64 + ni * 8 + 2 * q;
                const int hh = c0 >> 6, d0 = c0 & 63;
                __half* bp = Ch + ((size_t)(bi * H + hh) * D) * T;
                bp[(size_t)d0 * T + tl]           = __float2half(acc[mi][ni][0]);
                bp[(size_t)(d0 + 1) * T + tl]     = __float2half(acc[mi][ni][1]);
                bp[(size_t)d0 * T + tl + 8]       = __float2half(acc[mi][ni][2]);
                bp[(size_t)(d0 + 1) * T + tl + 8] = __float2half(acc[mi][ni][3]);
            }
        }
    } else {
        // Q: x0.125, dim-pair-interleaved (for direct LDG.64 a-frags)
        #pragma unroll
        for (int mi = 0; mi < 4; mi++) {
            const int r0 = bm + wr * 64 + mi * 16 + g;
            #pragma unroll
            for (int ni = 0; ni < 8; ni++) {
                const int base = bn + wc * 64 + ((ni >> 1) << 4) + 4*q + 2*(ni & 1);
                *(__half2*)(Ch + (size_t)r0 * E + base) =
                    __floats2half2_rn(0.125f * acc[mi][ni][0], 0.125f * acc[mi][ni][1]);
                *(__half2*)(Ch + (size_t)(r0+8) * E + base) =
                    __floats2half2_rn(0.125f * acc[mi][ni][2], 0.125f * acc[mi][ni][3]);
            }
        }
    }
}

__global__ __launch_bounds__(256, 1) void gemm_qkv() {
    extern __shared__ __half sg[];
    if (blockIdx.z == 0)      gemm_core(g_haq, g_hwq, nullptr, g_q,  2, sg);
    else if (blockIdx.z == 1) gemm_core(g_hak, g_hwk, nullptr, g_k,  3, sg);
    else                      gemm_core(g_hav, g_hwv, nullptr, g_vT, 4, sg);
}

__global__ __launch_bounds__(256, 1) void gemm_out(float* __restrict__ C) {
    extern __shared__ __half sg[];
    gemm_core(g_attn, g_hwo, C, nullptr, 0, sg);
}

// ===========================================================================
// Causal flash attention, fp16 m16n8k16, fp32 accum.
// K/V fragments via ldmatrix.x4 from plain row-major smem (128-B rows,
// chunk-XOR swizzle). 2 LDSM.x4 per nt per pass: 32 loads/tile (was 64).
// P acc layout == A-frag layout (no shuffles). 256 thr, 128 q-rows, 2 CTA/SM.
// ===========================================================================
#define AKB 8192                          // bytes per 64x128B buffer
#define A_SMEM (4*AKB)                    // K0,K1,V0,V1 = 32768 B

__global__ __launch_bounds__(256, 2) void attn_tc() {
    extern __shared__ __half sh[];
    const uint32_t sbase = su32(sh);

    const int tid = threadIdx.x;
    const int w = tid >> 5, lane = tid & 31;
    const int g = lane >> 2, q = lane & 3;
    const int b = blockIdx.y / H, h = blockIdx.y % H;
    const int qt = gridDim.x - 1 - blockIdx.x;
    const int qbase = qt * 128;
    const int jmax = 2 * qt + 1;

    const __half* Kg  = g_k + (size_t)(b * T) * E + h * D;
    const __half* Vtg = g_vT + (size_t)((b * H + h) * D) * T;

    // Q a-frags (fp16, interleaved, 0.125 pre-folded): 8 LDG.64
    const __half* Q0 = g_q + (size_t)(b * T + qbase + w * 16 + g) * E + h * D;
    uint32_t qa[4][4];
    #pragma unroll
    for (int kc = 0; kc < 4; kc++) {
        uint2 x0 = *(const uint2*)&Q0[kc * 16 + 4 * q];
        uint2 x1 = *(const uint2*)&Q0[(size_t)8 * E + kc * 16 + 4 * q];
        qa[kc][0] = x0.x; qa[kc][1] = x1.x; qa[kc][2] = x0.y; qa[kc][3] = x1.y;
    }

    auto stage = [&](int j) {
        const int buf = j & 1;
        const int kbase = j * 64;
        const uint32_t kdst = sbase + buf * AKB;
        const uint32_t vdst = sbase + (2 + buf) * AKB;
        #pragma unroll
        for (int t = 0; t < 4; t++) {
            int c = tid + t * 256;               // 0..1023
            int row = (c & 511) >> 3, ch = c & 7;
            uint32_t sw = ((ch ^ (row & 7)) << 4);
            if (c < 512) {
                cp16(kdst + row * 128 + sw,
                     Kg + (size_t)(kbase + row) * E + ch * 8);
            } else {
                cp16(vdst + row * 128 + sw,
                     Vtg + (size_t)row * T + kbase + ch * 8);
            }
        }
        cp_commit();
    };

    float oacc[8][4];
    #pragma unroll
    for (int nt = 0; nt < 8; nt++)
        #pragma unroll
        for (int e = 0; e < 4; e++) oacc[nt][e] = 0.f;

    float m0 = -INFINITY, m1 = -INFINITY, l0 = 0.f, l1 = 0.f;
    const int r0g = qbase + w * 16 + g, r1g = r0g + 8;
    const int wmaxrow = qbase + w * 16 + 15;

    // ldmatrix lane address components (rows = nt*8 + (lane&7))
    const int lrow = lane & 7;
    const int lgrp = lane >> 3;                  // chunk group 0..3
    const uint32_t off1 = (uint32_t)((lgrp ^ lrow) << 4);          // k 0..31
    const uint32_t off2 = (uint32_t)(((lgrp + 4) ^ lrow) << 4);    // k 32..63
    const uint32_t rbase = (uint32_t)(lrow * 128);

    stage(0);

    for (int j = 0; j <= jmax; j++) {
        __syncthreads();
        if (j < jmax) stage(j + 1);
        else          cp_commit();
        cp_wait<1>();
        __syncthreads();

        const int kbase = j * 64;
        if (kbase > wmaxrow) continue;

        const uint32_t Ks = sbase + (j & 1) * AKB + rbase;
        const uint32_t Vs = sbase + (2 + (j & 1)) * AKB + rbase;

        // S = Q @ K^T : 16 LDSM.x4 + 32 mma
        float sacc[8][4];
        #pragma unroll
        for (int nt = 0; nt < 8; nt++) {
            #pragma unroll
            for (int e = 0; e < 4; e++) sacc[nt][e] = 0.f;
            const uint32_t ka = Ks + nt * (8 * 128);
            uint32_t b0, b1, b2, b3, b4, b5, b6, b7;
            ldsm4(b0, b1, b2, b3, ka + off1);
            ldsm4(b4, b5, b6, b7, ka + off2);
            mma16(sacc[nt], qa[0][0], qa[0][1], qa[0][2], qa[0][3], b0, b1);
            mma16(sacc[nt], qa[1][0], qa[1][1], qa[1][2], qa[1][3], b2, b3);
            mma16(sacc[nt], qa[2][0], qa[2][1], qa[2][2], qa[2][3], b4, b5);
            mma16(sacc[nt], qa[3][0], qa[3][1], qa[3][2], qa[3][3], b6, b7);
        }

        if (kbase + 63 > r0g) {
            #pragma unroll
            for (int nt = 0; nt < 8; nt++) {
                #pragma unroll
                for (int e = 0; e < 2; e++) {
                    int colg = kbase + nt * 8 + 2 * q + e;
                    if (colg > r0g) sacc[nt][e]     = -INFINITY;
                    if (colg > r1g) sacc[nt][2 + e] = -INFINITY;
                }
            }
        }

        // Online softmax
        float mx0 = -INFINITY, mx1 = -INFINITY;
        #pragma unroll
        for (int nt = 0; nt < 8; nt++) {
            mx0 = fmaxf(mx0, fmaxf(sacc[nt][0], sacc[nt][1]));
            mx1 = fmaxf(mx1, fmaxf(sacc[nt][2], sacc[nt][3]));
        }
        mx0 = fmaxf(mx0, __shfl_xor_sync(0xffffffffu, mx0, 1));
        mx0 = fmaxf(mx0, __shfl_xor_sync(0xffffffffu, mx0, 2));
        mx1 = fmaxf(mx1, __shfl_xor_sync(0xffffffffu, mx1, 1));
        mx1 = fmaxf(mx1, __shfl_xor_sync(0xffffffffu, mx1, 2));
        float mn0 = fmaxf(m0, mx0), mn1 = fmaxf(m1, mx1);
        float sc0 = __expf(m0 - mn0), sc1 = __expf(m1 - mn1);

        float s0 = 0.f, s1 = 0.f;
        uint32_t ph[8][2];
        #pragma unroll
        for (int nt = 0; nt < 8; nt++) {
            float p0 = __expf(sacc[nt][0] - mn0);
            float p1 = __expf(sacc[nt][1] - mn0);
            float p2 = __expf(sacc[nt][2] - mn1);
            float p3 = __expf(sacc[nt][3] - mn1);
            s0 += p0 + p1; s1 += p2 + p3;
            ph[nt][0] = h2u(__floats2half2_rn(p0, p1));
            ph[nt][1] = h2u(__floats2half2_rn(p2, p3));
        }
        s0 += __shfl_xor_sync(0xffffffffu, s0, 1);
        s0 += __shfl_xor_sync(0xffffffffu, s0, 2);
        s1 += __shfl_xor_sync(0xffffffffu, s1, 1);
        s1 += __shfl_xor_sync(0xffffffffu, s1, 2);
        l0 = l0 * sc0 + s0; l1 = l1 * sc1 + s1;
        m0 = mn0; m1 = mn1;
        #pragma unroll
        for (int nt = 0; nt < 8; nt++) {
            oacc[nt][0] *= sc0; oacc[nt][1] *= sc0;
            oacc[nt][2] *= sc1; oacc[nt][3] *= sc1;
        }

        // O += P @ V : 16 LDSM.x4 + 32 mma (P acc layout == A-frag layout)
        #pragma unroll
        for (int nt = 0; nt < 8; nt++) {
            const uint32_t va = Vs + nt * (8 * 128);
            uint32_t b0, b1, b2, b3, b4, b5, b6, b7;
            ldsm4(b0, b1, b2, b3, va + off1);
            ldsm4(b4, b5, b6, b7, va + off2);
            mma16(oacc[nt], ph[0][0], ph[0][1], ph[1][0], ph[1][1], b0, b1);
            mma16(oacc[nt], ph[2][0], ph[2][1], ph[3][0], ph[3][1], b2, b3);
            mma16(oacc[nt], ph[4][0], ph[4][1], ph[5][0], ph[5][1], b4, b5);
            mma16(oacc[nt], ph[6][0], ph[6][1], ph[7][0], ph[7][1], b6, b7);
        }
    }

    // Epilogue: plain row-major fp16 (gemm_out consumes via ldmatrix)
    const float inv0 = 1.f / l0, inv1 = 1.f / l1;
    __half* O0 = g_attn + ((size_t)(b * T + r0g)) * E + h * D;
    __half* O1 = g_attn + ((size_t)(b * T + r1g)) * E + h * D;
    #pragma unroll
    for (int nt = 0; nt < 8; nt++) {
        *(__half2*)(O0 + nt * 8 + 2 * q) =
            __floats2half2_rn(oacc[nt][0] * inv0, oacc[nt][1] * inv0);
        *(__half2*)(O1 + nt * 8 + 2 * q) =
            __floats2half2_rn(oacc[nt][2] * inv1, oacc[nt][3] * inv1);
    }
}

// ===========================================================================
// Inputs: queries, keys, values, mask(unused), Wq, Wk, Wv, Wo
// ===========================================================================
extern "C" void kernel_launch(void* const* d_in, const int* in_sizes, int n_in,
                              void* d_out, int out_size) {
    const float* queries = (const float*)d_in[0];
    const float* keys    = (const float*)d_in[1];
    const float* values  = (const float*)d_in[2];
    const float* Wq      = (const float*)d_in[4];
    const float* Wk      = (const float*)d_in[5];
    const float* Wv      = (const float*)d_in[6];
    const float* Wo      = (const float*)d_in[7];

    __half *haq, *hak, *hav, *hwq, *hwk, *hwv, *hwo;
    cudaGetSymbolAddress((void**)&haq, g_haq);
    cudaGetSymbolAddress((void**)&hak, g_hak);
    cudaGetSymbolAddress((void**)&hav, g_hav);
    cudaGetSymbolAddress((void**)&hwq, g_hwq);
    cudaGetSymbolAddress((void**)&hwk, g_hwk);
    cudaGetSymbolAddress((void**)&hwv, g_hwv);
    cudaGetSymbolAddress((void**)&hwo, g_hwo);

    static bool attr_set = false;
    if (!attr_set) {
        cudaFuncSetAttribute(gemm_qkv, cudaFuncAttributeMaxDynamicSharedMemorySize, (int)G_SMEM);
        cudaFuncSetAttribute(gemm_out, cudaFuncAttributeMaxDynamicSharedMemorySize, (int)G_SMEM);
        cudaFuncSetAttribute(attn_tc,  cudaFuncAttributeMaxDynamicSharedMemorySize, (int)A_SMEM);
        attr_set = true;
    }

    PPArgs pa;
    const int NG_IN = BSZ * T * E / 8;
    const int NG_W  = E * E / 8;
    pa.src[0] = queries; pa.dst[0] = haq; pa.ngrp[0] = NG_IN;
    pa.src[1] = keys;    pa.dst[1] = hak; pa.ngrp[1] = NG_IN;
    pa.src[2] = values;  pa.dst[2] = hav; pa.ngrp[2] = NG_IN;
    pa.src[3] = Wq;      pa.dst[3] = hwq; pa.ngrp[3] = NG_W;
    pa.src[4] = Wk;      pa.dst[4] = hwk; pa.ngrp[4] = NG_W;
    pa.src[5] = Wv;      pa.dst[5] = hwv; pa.ngrp[5] = NG_W;
    pa.src[6] = Wo;      pa.dst[6] = hwo; pa.ngrp[6] = NG_W;
    prepass<<<dim3(NG_IN / 256, 1, 7), 256>>>(pa);

    dim3 gq(E / NT, (BSZ * T) / MT, 3);     // (8, 16, 3) = 384 CTAs
    gemm_qkv<<<gq, 256, G_SMEM>>>();

    attn_tc<<<dim3(T / 128, BSZ * H), 256, A_SMEM>>>();

    dim3 gg(E / NT, (BSZ * T) / MT);        // (8, 16) = 128 CTAs
    gemm_out<<<gg, 256, G_SMEM>>>((float*)d_out);
}